// round 15
// baseline (speedup 1.0000x reference)
#include <cuda_runtime.h>

// Problem constants (fixed by the reference)
#define BSZ    2
#define LEN    2048
#define DQ     512
#define SQ     4
#define SH     2                 // s-lanes per thread (K1 and K3)
#define NC     128               // fine chunks along L (all kernels)
#define CHUNKF (LEN / NC)        // 16 steps per fine chunk
#define NCL    (NC / 32)         // fine chunks per lane in K2 warp scan (4)
#define EPSQ   1e-6f

// Scratch: chunk summaries and carries, laid out [b][chunk][s][d].
__device__ float4 g_Q  [BSZ * NC * SQ * DQ];
__device__ float4 g_H  [BSZ * NC * SQ * DQ];
__device__ float4 g_Hin[BSZ * NC * SQ * DQ];

// ---------------------------------------------------------------------------
// Quaternion helpers
// ---------------------------------------------------------------------------
__device__ __forceinline__ float4 qmuladd(const float4 a, const float4 b, const float4 c) {
    float4 r;
    r.x = fmaf(a.x, b.x, fmaf(-a.y, b.y, fmaf(-a.z, b.z, fmaf(-a.w, b.w, c.x))));
    r.y = fmaf(a.x, b.y, fmaf( a.y, b.x, fmaf( a.z, b.w, fmaf(-a.w, b.z, c.y))));
    r.z = fmaf(a.x, b.z, fmaf(-a.y, b.w, fmaf( a.z, b.x, fmaf( a.w, b.y, c.z))));
    r.w = fmaf(a.x, b.w, fmaf( a.y, b.z, fmaf(-a.z, b.y, fmaf( a.w, b.x, c.w))));
    return r;
}
__device__ __forceinline__ float4 qmul(const float4 a, const float4 b) {
    return qmuladd(a, b, make_float4(0.f, 0.f, 0.f, 0.f));
}
__device__ __forceinline__ float4 add4(const float4 a, const float4 b) {
    return make_float4(a.x + b.x, a.y + b.y, a.z + b.z, a.w + b.w);
}

// Approximate reciprocal (no Newton step): rel err ~2.4e-7, fine vs 1e-3 tol.
__device__ __forceinline__ float frcp(float x) {
    float r; asm("rcp.approx.f32 %0, %1;" : "=f"(r) : "f"(x)); return r;
}

// Per-(d,s) transition invariants: pax = +0.5*exp(A_log) (= -a_x),
// av = 0.5*(A_i,A_j,A_k), S = |av|^2.
struct AInv { float pax, ay, az, aw, S; };

// Optimized per-step transition quaternion:
//   omr = 1 + dt*pax ; vve = dt^2*S + eps ; n2 = omr^2 + vve ; r2 = 2/n2
//   q = (omr*r2 - 1, (dt*r2)*av)
__device__ __forceinline__ float4 step_q(const float dtv, const float dt2,
                                         const AInv& a) {
    const float omr = fmaf(dtv, a.pax, 1.0f);
    const float vve = fmaf(dt2, a.S, EPSQ);
    const float n2  = fmaf(omr, omr, vve);
    const float r2  = frcp(n2) * 2.0f;
    const float e   = dtv * r2;
    return make_float4(fmaf(omr, r2, -1.0f), e * a.ay, e * a.az, e * a.aw);
}

__device__ __forceinline__ AInv load_ainv(const float* __restrict__ A_log,
                                          const float* __restrict__ A_i,
                                          const float* __restrict__ A_j,
                                          const float* __restrict__ A_k,
                                          int ai) {
    AInv r;
    r.pax = 0.5f * __expf(A_log[ai]);
    r.ay  = 0.5f * A_i[ai];
    r.az  = 0.5f * A_j[ai];
    r.aw  = 0.5f * A_k[ai];
    r.S   = fmaf(r.ay, r.ay, fmaf(r.az, r.az, r.aw * r.aw));
    return r;
}

__device__ __forceinline__ float4 shfl_up4(const float4 v, int off) {
    float4 r;
    r.x = __shfl_up_sync(0xffffffffu, v.x, off);
    r.y = __shfl_up_sync(0xffffffffu, v.y, off);
    r.z = __shfl_up_sync(0xffffffffu, v.z, off);
    r.w = __shfl_up_sync(0xffffffffu, v.w, off);
    return r;
}

// SH=2 thread decomposition: lane bits [0:4)=d_low4, bit4=s-half, d_hi, c, b.
struct DeH { int b, c, d, s0, hbit; };
__device__ __forceinline__ DeH decompH(int gt) {
    DeH r;
    const int lane16 = gt & 15;
    r.hbit = (gt >> 4) & 1;
    const int rest = gt >> 5;
    r.d = ((rest & 31) << 4) + lane16;
    r.c = (rest >> 5) & (NC - 1);
    r.b = rest >> 12;
    r.s0 = r.hbit * SH;
    return r;
}

// ---------------------------------------------------------------------------
// K1: per-(b, chunk, d, s-half) thread — chunk transforms (Q, H).
//     minBlocks=5 caps regs at 51 -> 5 CTAs/SM (40 warps).
// ---------------------------------------------------------------------------
__global__ void __launch_bounds__(256, 5)
k_summary(const float* __restrict__ u, const float* __restrict__ dt,
          const float* __restrict__ Bin,
          const float* __restrict__ A_log, const float* __restrict__ A_i,
          const float* __restrict__ A_j,  const float* __restrict__ A_k)
{
    const DeH de = decompH(blockIdx.x * blockDim.x + threadIdx.x);
    const int d = de.d, c = de.c, b = de.b, s0 = de.s0;

    AInv av[SH];
#pragma unroll
    for (int s = 0; s < SH; s++)
        av[s] = load_ainv(A_log, A_i, A_j, A_k, d * SQ + s0 + s);

    const float4* __restrict__ u4 = (const float4*)u;
    const float4* __restrict__ B4 = (const float4*)Bin;

    const int t0 = c * CHUNKF;
    float4 Q[SH], H[SH];

    {   // peel first step: Q = q, H = q(x)Bu0 + Bu0
        const int td = b * LEN + t0;
        const float  dtv = dt[td * DQ + d];
        const float4 uu  = u4[td * DQ + d];
        const float  hdt = 0.5f * dtv;
        const float  dt2 = dtv * dtv;
        const float4 us  = make_float4(uu.x * hdt, uu.y * hdt, uu.z * hdt, uu.w * hdt);
#pragma unroll
        for (int s = 0; s < SH; s++) {
            const float4 Bq = B4[td * SQ + s0 + s];
            const float4 q  = step_q(dtv, dt2, av[s]);
            const float4 Bu0 = qmul(Bq, us);
            Q[s] = q;
            H[s] = qmuladd(q, Bu0, Bu0);
        }
    }

#pragma unroll 2
    for (int i = 1; i < CHUNKF; i++) {
        const int td = b * LEN + t0 + i;
        const float  dtv = dt[td * DQ + d];
        const float4 uu  = u4[td * DQ + d];
        const float  hdt = 0.5f * dtv;
        const float  dt2 = dtv * dtv;
        const float4 us  = make_float4(uu.x * hdt, uu.y * hdt, uu.z * hdt, uu.w * hdt);
#pragma unroll
        for (int s = 0; s < SH; s++) {
            const float4 Bq = B4[td * SQ + s0 + s];
            const float4 q  = step_q(dtv, dt2, av[s]);
            const float4 Bu0 = qmul(Bq, us);
            H[s] = qmuladd(q, add4(H[s], Bu0), Bu0);
            Q[s] = qmul(q, Q[s]);
        }
    }

#pragma unroll
    for (int s = 0; s < SH; s++) {
        const int idx = ((b * NC + c) * SQ + s0 + s) * DQ + d;
        g_Q[idx] = Q[s];
        g_H[idx] = H[s];
    }
}

// ---------------------------------------------------------------------------
// K2: warp-parallel affine scan. One warp per (b,s,d) chain; each lane owns
//     NCL=4 consecutive fine chunks. Local compose -> shfl_up scan -> replay.
// ---------------------------------------------------------------------------
__global__ void __launch_bounds__(256)
k_carry()
{
    const int gt = blockIdx.x * blockDim.x + threadIdx.x;
    const int lane = gt & 31;
    const int w = gt >> 5;                 // chain id in [0, BSZ*SQ*DQ)
    const int d = w & (DQ - 1);
    const int s = (w >> 9) & (SQ - 1);
    const int b = w >> 11;

    const int cstride = SQ * DQ;
    const int base = (b * NC * SQ + s) * DQ + d;
    const int c0 = lane * NCL;

    float4 Qc[NCL], Hc[NCL];
#pragma unroll
    for (int j = 0; j < NCL; j++) {
        const int idx = base + (c0 + j) * cstride;
        Qc[j] = g_Q[idx];
        Hc[j] = g_H[idx];
    }

    // Local inclusive composition over this lane's 4 chunks.
    float4 Qs = Qc[0], Hs = Hc[0];
#pragma unroll
    for (int j = 1; j < NCL; j++) {
        Hs = qmuladd(Qc[j], Hs, Hc[j]);
        Qs = qmul(Qc[j], Qs);
    }

    // Warp inclusive scan of the affine pair.
#pragma unroll
    for (int off = 1; off < 32; off <<= 1) {
        const float4 Qp = shfl_up4(Qs, off);
        const float4 Hp = shfl_up4(Hs, off);
        if (lane >= off) {
            Hs = qmuladd(Qs, Hp, Hs);   // pre-update Qs = current segment
            Qs = qmul(Qs, Qp);
        }
    }

    // Exclusive prefix = inclusive of lane-1 (identity at lane 0).
    float4 h = shfl_up4(Hs, 1);
    if (lane == 0) h = make_float4(0.f, 0.f, 0.f, 0.f);

    // Replay: emit carry-in for each owned chunk.
#pragma unroll
    for (int j = 0; j < NCL; j++) {
        const int idx = base + (c0 + j) * cstride;
        g_Hin[idx] = h;
        h = qmuladd(Qc[j], h, Hc[j]);
    }
}

// ---------------------------------------------------------------------------
// K3: per-(b, chunk, d, s-half) thread — recompute with carry, emit y.
//     Pair-sum over s-halves via shfl_xor(16); hbit==0 lanes store float4.
//     minBlocks=5 caps regs at 51.
// ---------------------------------------------------------------------------
__global__ void __launch_bounds__(256, 5)
k_final(const float* __restrict__ u, const float* __restrict__ dt,
        const float* __restrict__ Bin, const float* __restrict__ Cin,
        const float* __restrict__ A_log, const float* __restrict__ A_i,
        const float* __restrict__ A_j,  const float* __restrict__ A_k,
        float* __restrict__ out)
{
    const DeH de = decompH(blockIdx.x * blockDim.x + threadIdx.x);
    const int d = de.d, c = de.c, b = de.b, s0 = de.s0;

    AInv av[SH];
#pragma unroll
    for (int s = 0; s < SH; s++)
        av[s] = load_ainv(A_log, A_i, A_j, A_k, d * SQ + s0 + s);

    float4 h[SH];
#pragma unroll
    for (int s = 0; s < SH; s++)
        h[s] = g_Hin[((b * NC + c) * SQ + s0 + s) * DQ + d];

    const float4* __restrict__ u4 = (const float4*)u;
    const float4* __restrict__ B4 = (const float4*)Bin;
    const float4* __restrict__ C4 = (const float4*)Cin;
    float4* __restrict__ o4 = (float4*)out;

    const int t0 = c * CHUNKF;
#pragma unroll 2
    for (int i = 0; i < CHUNKF; i++) {
        const int td = b * LEN + t0 + i;
        const float  dtv = dt[td * DQ + d];
        const float4 uu  = u4[td * DQ + d];
        const float  hdt = 0.5f * dtv;
        const float  dt2 = dtv * dtv;
        const float4 us  = make_float4(uu.x * hdt, uu.y * hdt, uu.z * hdt, uu.w * hdt);
        float4 y = make_float4(0.f, 0.f, 0.f, 0.f);
#pragma unroll
        for (int s = 0; s < SH; s++) {
            const float4 Bq = B4[td * SQ + s0 + s];
            const float4 Cq = C4[td * SQ + s0 + s];
            const float4 q  = step_q(dtv, dt2, av[s]);
            const float4 Bu0 = qmul(Bq, us);
            h[s] = qmuladd(q, add4(h[s], Bu0), Bu0);
            y = qmuladd(Cq, h[s], y);
        }
        // Pair-reduce across s-halves (lane bit 4).
        y.x += __shfl_xor_sync(0xffffffffu, y.x, 16);
        y.y += __shfl_xor_sync(0xffffffffu, y.y, 16);
        y.z += __shfl_xor_sync(0xffffffffu, y.z, 16);
        y.w += __shfl_xor_sync(0xffffffffu, y.w, 16);
        if (de.hbit == 0)
            o4[td * DQ + d] = y;
    }
}

// ---------------------------------------------------------------------------
// Launch (single stream)
// ---------------------------------------------------------------------------
extern "C" void kernel_launch(void* const* d_in, const int* in_sizes, int n_in,
                              void* d_out, int out_size)
{
    const float* u     = (const float*)d_in[0];
    const float* dt    = (const float*)d_in[1];
    const float* Bin   = (const float*)d_in[2];
    const float* Cin   = (const float*)d_in[3];
    const float* A_log = (const float*)d_in[4];
    const float* A_i   = (const float*)d_in[5];
    const float* A_j   = (const float*)d_in[6];
    const float* A_k   = (const float*)d_in[7];
    float* out = (float*)d_out;

    const int k13_threads = BSZ * NC * DQ * 2;      // 262144
    const int k2_threads  = BSZ * SQ * DQ * 32;     // 131072 (warp per chain)

    k_summary<<<k13_threads / 256, 256>>>(u, dt, Bin, A_log, A_i, A_j, A_k);
    k_carry<<<k2_threads / 256, 256>>>();
    k_final<<<k13_threads / 256, 256>>>(u, dt, Bin, Cin, A_log, A_i, A_j, A_k, out);
}

// round 16
// speedup vs baseline: 1.1735x; 1.1735x over previous
#include <cuda_runtime.h>

// Problem constants (fixed by the reference)
#define BSZ    2
#define LEN    2048
#define DQ     512
#define SQ     4
#define SH     2                 // s-lanes per thread (K1 and K3)
#define NC     128               // fine chunks along L (all kernels)
#define CHUNKF (LEN / NC)        // 16 steps per fine chunk
#define NCL    (NC / 32)         // fine chunks per lane in K2 warp scan (4)
#define EPSQ   1e-6f

// Scratch: chunk summaries and carries, laid out [b][chunk][s][d].
__device__ float4 g_Q  [BSZ * NC * SQ * DQ];
__device__ float4 g_H  [BSZ * NC * SQ * DQ];
__device__ float4 g_Hin[BSZ * NC * SQ * DQ];

// ---------------------------------------------------------------------------
// Quaternion helpers
// ---------------------------------------------------------------------------
__device__ __forceinline__ float4 qmuladd(const float4 a, const float4 b, const float4 c) {
    float4 r;
    r.x = fmaf(a.x, b.x, fmaf(-a.y, b.y, fmaf(-a.z, b.z, fmaf(-a.w, b.w, c.x))));
    r.y = fmaf(a.x, b.y, fmaf( a.y, b.x, fmaf( a.z, b.w, fmaf(-a.w, b.z, c.y))));
    r.z = fmaf(a.x, b.z, fmaf(-a.y, b.w, fmaf( a.z, b.x, fmaf( a.w, b.y, c.z))));
    r.w = fmaf(a.x, b.w, fmaf( a.y, b.z, fmaf(-a.z, b.y, fmaf( a.w, b.x, c.w))));
    return r;
}
__device__ __forceinline__ float4 qmul(const float4 a, const float4 b) {
    return qmuladd(a, b, make_float4(0.f, 0.f, 0.f, 0.f));
}
__device__ __forceinline__ float4 add4(const float4 a, const float4 b) {
    return make_float4(a.x + b.x, a.y + b.y, a.z + b.z, a.w + b.w);
}

// Approximate reciprocal (no Newton step): rel err ~2.4e-7, fine vs 1e-3 tol.
__device__ __forceinline__ float frcp(float x) {
    float r; asm("rcp.approx.f32 %0, %1;" : "=f"(r) : "f"(x)); return r;
}

// Per-(d,s) transition invariants: pax = +0.5*exp(A_log) (= -a_x),
// av = 0.5*(A_i,A_j,A_k), S = |av|^2.
struct AInv { float pax, ay, az, aw, S; };

// Optimized per-step transition quaternion:
//   omr = 1 + dt*pax ; vve = dt^2*S + eps ; n2 = omr^2 + vve ; r2 = 2/n2
//   q = (omr*r2 - 1, (dt*r2)*av)
__device__ __forceinline__ float4 step_q(const float dtv, const float dt2,
                                         const AInv& a) {
    const float omr = fmaf(dtv, a.pax, 1.0f);
    const float vve = fmaf(dt2, a.S, EPSQ);
    const float n2  = fmaf(omr, omr, vve);
    const float r2  = frcp(n2) * 2.0f;
    const float e   = dtv * r2;
    return make_float4(fmaf(omr, r2, -1.0f), e * a.ay, e * a.az, e * a.aw);
}

__device__ __forceinline__ AInv load_ainv(const float* __restrict__ A_log,
                                          const float* __restrict__ A_i,
                                          const float* __restrict__ A_j,
                                          const float* __restrict__ A_k,
                                          int ai) {
    AInv r;
    r.pax = 0.5f * __expf(A_log[ai]);
    r.ay  = 0.5f * A_i[ai];
    r.az  = 0.5f * A_j[ai];
    r.aw  = 0.5f * A_k[ai];
    r.S   = fmaf(r.ay, r.ay, fmaf(r.az, r.az, r.aw * r.aw));
    return r;
}

__device__ __forceinline__ float4 shfl_up4(const float4 v, int off) {
    float4 r;
    r.x = __shfl_up_sync(0xffffffffu, v.x, off);
    r.y = __shfl_up_sync(0xffffffffu, v.y, off);
    r.z = __shfl_up_sync(0xffffffffu, v.z, off);
    r.w = __shfl_up_sync(0xffffffffu, v.w, off);
    return r;
}

// SH=2 thread decomposition: lane bits [0:4)=d_low4, bit4=s-half, d_hi, c, b.
struct DeH { int b, c, d, s0, hbit; };
__device__ __forceinline__ DeH decompH(int gt) {
    DeH r;
    const int lane16 = gt & 15;
    r.hbit = (gt >> 4) & 1;
    const int rest = gt >> 5;
    r.d = ((rest & 31) << 4) + lane16;
    r.c = (rest >> 5) & (NC - 1);
    r.b = rest >> 12;
    r.s0 = r.hbit * SH;
    return r;
}

// ---------------------------------------------------------------------------
// K1: per-(b, chunk, d, s-half) thread — chunk transforms (Q, H).
//     (256,4): 64-reg cap, 4 CTAs/SM — measured optimum.
// ---------------------------------------------------------------------------
__global__ void __launch_bounds__(256, 4)
k_summary(const float* __restrict__ u, const float* __restrict__ dt,
          const float* __restrict__ Bin,
          const float* __restrict__ A_log, const float* __restrict__ A_i,
          const float* __restrict__ A_j,  const float* __restrict__ A_k)
{
    const DeH de = decompH(blockIdx.x * blockDim.x + threadIdx.x);
    const int d = de.d, c = de.c, b = de.b, s0 = de.s0;

    AInv av[SH];
#pragma unroll
    for (int s = 0; s < SH; s++)
        av[s] = load_ainv(A_log, A_i, A_j, A_k, d * SQ + s0 + s);

    const float4* __restrict__ u4 = (const float4*)u;
    const float4* __restrict__ B4 = (const float4*)Bin;

    const int t0 = c * CHUNKF;
    float4 Q[SH], H[SH];

    {   // peel first step: Q = q, H = q(x)Bu0 + Bu0
        const int td = b * LEN + t0;
        const float  dtv = dt[td * DQ + d];
        const float4 uu  = u4[td * DQ + d];
        const float  hdt = 0.5f * dtv;
        const float  dt2 = dtv * dtv;
        const float4 us  = make_float4(uu.x * hdt, uu.y * hdt, uu.z * hdt, uu.w * hdt);
#pragma unroll
        for (int s = 0; s < SH; s++) {
            const float4 Bq = B4[td * SQ + s0 + s];
            const float4 q  = step_q(dtv, dt2, av[s]);
            const float4 Bu0 = qmul(Bq, us);
            Q[s] = q;
            H[s] = qmuladd(q, Bu0, Bu0);
        }
    }

#pragma unroll 2
    for (int i = 1; i < CHUNKF; i++) {
        const int td = b * LEN + t0 + i;
        const float  dtv = dt[td * DQ + d];
        const float4 uu  = u4[td * DQ + d];
        const float  hdt = 0.5f * dtv;
        const float  dt2 = dtv * dtv;
        const float4 us  = make_float4(uu.x * hdt, uu.y * hdt, uu.z * hdt, uu.w * hdt);
#pragma unroll
        for (int s = 0; s < SH; s++) {
            const float4 Bq = B4[td * SQ + s0 + s];
            const float4 q  = step_q(dtv, dt2, av[s]);
            const float4 Bu0 = qmul(Bq, us);
            H[s] = qmuladd(q, add4(H[s], Bu0), Bu0);
            Q[s] = qmul(q, Q[s]);
        }
    }

#pragma unroll
    for (int s = 0; s < SH; s++) {
        const int idx = ((b * NC + c) * SQ + s0 + s) * DQ + d;
        g_Q[idx] = Q[s];
        g_H[idx] = H[s];
    }
}

// ---------------------------------------------------------------------------
// K2: warp-parallel affine scan. One warp per (b,s,d) chain; each lane owns
//     NCL=4 consecutive fine chunks. Local compose -> shfl_up scan -> replay.
// ---------------------------------------------------------------------------
__global__ void __launch_bounds__(256)
k_carry()
{
    const int gt = blockIdx.x * blockDim.x + threadIdx.x;
    const int lane = gt & 31;
    const int w = gt >> 5;                 // chain id in [0, BSZ*SQ*DQ)
    const int d = w & (DQ - 1);
    const int s = (w >> 9) & (SQ - 1);
    const int b = w >> 11;

    const int cstride = SQ * DQ;
    const int base = (b * NC * SQ + s) * DQ + d;
    const int c0 = lane * NCL;

    float4 Qc[NCL], Hc[NCL];
#pragma unroll
    for (int j = 0; j < NCL; j++) {
        const int idx = base + (c0 + j) * cstride;
        Qc[j] = g_Q[idx];
        Hc[j] = g_H[idx];
    }

    // Local inclusive composition over this lane's 4 chunks.
    float4 Qs = Qc[0], Hs = Hc[0];
#pragma unroll
    for (int j = 1; j < NCL; j++) {
        Hs = qmuladd(Qc[j], Hs, Hc[j]);
        Qs = qmul(Qc[j], Qs);
    }

    // Warp inclusive scan of the affine pair.
#pragma unroll
    for (int off = 1; off < 32; off <<= 1) {
        const float4 Qp = shfl_up4(Qs, off);
        const float4 Hp = shfl_up4(Hs, off);
        if (lane >= off) {
            Hs = qmuladd(Qs, Hp, Hs);   // pre-update Qs = current segment
            Qs = qmul(Qs, Qp);
        }
    }

    // Exclusive prefix = inclusive of lane-1 (identity at lane 0).
    float4 h = shfl_up4(Hs, 1);
    if (lane == 0) h = make_float4(0.f, 0.f, 0.f, 0.f);

    // Replay: emit carry-in for each owned chunk.
#pragma unroll
    for (int j = 0; j < NCL; j++) {
        const int idx = base + (c0 + j) * cstride;
        g_Hin[idx] = h;
        h = qmuladd(Qc[j], h, Hc[j]);
    }
}

// ---------------------------------------------------------------------------
// K3: per-(b, chunk, d, s-half) thread — recompute with carry, emit y.
//     Output stored with streaming policy (__stcs) so the 64MB y-stream does
//     not evict u/dt from L2 between graph replays.
// ---------------------------------------------------------------------------
__global__ void __launch_bounds__(256, 4)
k_final(const float* __restrict__ u, const float* __restrict__ dt,
        const float* __restrict__ Bin, const float* __restrict__ Cin,
        const float* __restrict__ A_log, const float* __restrict__ A_i,
        const float* __restrict__ A_j,  const float* __restrict__ A_k,
        float* __restrict__ out)
{
    const DeH de = decompH(blockIdx.x * blockDim.x + threadIdx.x);
    const int d = de.d, c = de.c, b = de.b, s0 = de.s0;

    AInv av[SH];
#pragma unroll
    for (int s = 0; s < SH; s++)
        av[s] = load_ainv(A_log, A_i, A_j, A_k, d * SQ + s0 + s);

    float4 h[SH];
#pragma unroll
    for (int s = 0; s < SH; s++)
        h[s] = g_Hin[((b * NC + c) * SQ + s0 + s) * DQ + d];

    const float4* __restrict__ u4 = (const float4*)u;
    const float4* __restrict__ B4 = (const float4*)Bin;
    const float4* __restrict__ C4 = (const float4*)Cin;
    float4* __restrict__ o4 = (float4*)out;

    const int t0 = c * CHUNKF;
#pragma unroll 2
    for (int i = 0; i < CHUNKF; i++) {
        const int td = b * LEN + t0 + i;
        const float  dtv = dt[td * DQ + d];
        const float4 uu  = u4[td * DQ + d];
        const float  hdt = 0.5f * dtv;
        const float  dt2 = dtv * dtv;
        const float4 us  = make_float4(uu.x * hdt, uu.y * hdt, uu.z * hdt, uu.w * hdt);
        float4 y = make_float4(0.f, 0.f, 0.f, 0.f);
#pragma unroll
        for (int s = 0; s < SH; s++) {
            const float4 Bq = B4[td * SQ + s0 + s];
            const float4 Cq = C4[td * SQ + s0 + s];
            const float4 q  = step_q(dtv, dt2, av[s]);
            const float4 Bu0 = qmul(Bq, us);
            h[s] = qmuladd(q, add4(h[s], Bu0), Bu0);
            y = qmuladd(Cq, h[s], y);
        }
        // Pair-reduce across s-halves (lane bit 4).
        y.x += __shfl_xor_sync(0xffffffffu, y.x, 16);
        y.y += __shfl_xor_sync(0xffffffffu, y.y, 16);
        y.z += __shfl_xor_sync(0xffffffffu, y.z, 16);
        y.w += __shfl_xor_sync(0xffffffffu, y.w, 16);
        if (de.hbit == 0)
            __stcs(&o4[td * DQ + d], y);   // streaming store: keep u/dt in L2
    }
}

// ---------------------------------------------------------------------------
// Launch (single stream)
// ---------------------------------------------------------------------------
extern "C" void kernel_launch(void* const* d_in, const int* in_sizes, int n_in,
                              void* d_out, int out_size)
{
    const float* u     = (const float*)d_in[0];
    const float* dt    = (const float*)d_in[1];
    const float* Bin   = (const float*)d_in[2];
    const float* Cin   = (const float*)d_in[3];
    const float* A_log = (const float*)d_in[4];
    const float* A_i   = (const float*)d_in[5];
    const float* A_j   = (const float*)d_in[6];
    const float* A_k   = (const float*)d_in[7];
    float* out = (float*)d_out;

    const int k13_threads = BSZ * NC * DQ * 2;      // 262144
    const int k2_threads  = BSZ * SQ * DQ * 32;     // 131072 (warp per chain)

    k_summary<<<k13_threads / 256, 256>>>(u, dt, Bin, A_log, A_i, A_j, A_k);
    k_carry<<<k2_threads / 256, 256>>>();
    k_final<<<k13_threads / 256, 256>>>(u, dt, Bin, Cin, A_log, A_i, A_j, A_k, out);
}

// round 17
// speedup vs baseline: 1.1740x; 1.0005x over previous
#include <cuda_runtime.h>

// Problem constants (fixed by the reference)
#define BSZ    2
#define LEN    2048
#define DQ     512
#define SQ     4
#define SH     2                 // s-lanes per thread (K1 and K3)
#define NC     128               // fine chunks along L (all kernels)
#define CHUNKF (LEN / NC)        // 16 steps per fine chunk
#define NCL    (NC / 32)         // fine chunks per lane in K2 warp scan (4)
#define EPSQ   1e-6f

// Scratch: chunk summaries and carries, laid out [b][chunk][s][d].
// All scratch is write-once/read-once per replay -> streamed through L2
// with evict-first policy (__stcs/__ldcs) so u/dt stay resident.
__device__ float4 g_Q  [BSZ * NC * SQ * DQ];
__device__ float4 g_H  [BSZ * NC * SQ * DQ];
__device__ float4 g_Hin[BSZ * NC * SQ * DQ];

// ---------------------------------------------------------------------------
// Quaternion helpers
// ---------------------------------------------------------------------------
__device__ __forceinline__ float4 qmuladd(const float4 a, const float4 b, const float4 c) {
    float4 r;
    r.x = fmaf(a.x, b.x, fmaf(-a.y, b.y, fmaf(-a.z, b.z, fmaf(-a.w, b.w, c.x))));
    r.y = fmaf(a.x, b.y, fmaf( a.y, b.x, fmaf( a.z, b.w, fmaf(-a.w, b.z, c.y))));
    r.z = fmaf(a.x, b.z, fmaf(-a.y, b.w, fmaf( a.z, b.x, fmaf( a.w, b.y, c.z))));
    r.w = fmaf(a.x, b.w, fmaf( a.y, b.z, fmaf(-a.z, b.y, fmaf( a.w, b.x, c.w))));
    return r;
}
__device__ __forceinline__ float4 qmul(const float4 a, const float4 b) {
    return qmuladd(a, b, make_float4(0.f, 0.f, 0.f, 0.f));
}
__device__ __forceinline__ float4 add4(const float4 a, const float4 b) {
    return make_float4(a.x + b.x, a.y + b.y, a.z + b.z, a.w + b.w);
}

// Approximate reciprocal (no Newton step): rel err ~2.4e-7, fine vs 1e-3 tol.
__device__ __forceinline__ float frcp(float x) {
    float r; asm("rcp.approx.f32 %0, %1;" : "=f"(r) : "f"(x)); return r;
}

// Per-(d,s) transition invariants: pax = +0.5*exp(A_log) (= -a_x),
// av = 0.5*(A_i,A_j,A_k), S = |av|^2.
struct AInv { float pax, ay, az, aw, S; };

// Optimized per-step transition quaternion:
//   omr = 1 + dt*pax ; vve = dt^2*S + eps ; n2 = omr^2 + vve ; r2 = 2/n2
//   q = (omr*r2 - 1, (dt*r2)*av)
__device__ __forceinline__ float4 step_q(const float dtv, const float dt2,
                                         const AInv& a) {
    const float omr = fmaf(dtv, a.pax, 1.0f);
    const float vve = fmaf(dt2, a.S, EPSQ);
    const float n2  = fmaf(omr, omr, vve);
    const float r2  = frcp(n2) * 2.0f;
    const float e   = dtv * r2;
    return make_float4(fmaf(omr, r2, -1.0f), e * a.ay, e * a.az, e * a.aw);
}

__device__ __forceinline__ AInv load_ainv(const float* __restrict__ A_log,
                                          const float* __restrict__ A_i,
                                          const float* __restrict__ A_j,
                                          const float* __restrict__ A_k,
                                          int ai) {
    AInv r;
    r.pax = 0.5f * __expf(A_log[ai]);
    r.ay  = 0.5f * A_i[ai];
    r.az  = 0.5f * A_j[ai];
    r.aw  = 0.5f * A_k[ai];
    r.S   = fmaf(r.ay, r.ay, fmaf(r.az, r.az, r.aw * r.aw));
    return r;
}

__device__ __forceinline__ float4 shfl_up4(const float4 v, int off) {
    float4 r;
    r.x = __shfl_up_sync(0xffffffffu, v.x, off);
    r.y = __shfl_up_sync(0xffffffffu, v.y, off);
    r.z = __shfl_up_sync(0xffffffffu, v.z, off);
    r.w = __shfl_up_sync(0xffffffffu, v.w, off);
    return r;
}

// SH=2 thread decomposition: lane bits [0:4)=d_low4, bit4=s-half, d_hi, c, b.
struct DeH { int b, c, d, s0, hbit; };
__device__ __forceinline__ DeH decompH(int gt) {
    DeH r;
    const int lane16 = gt & 15;
    r.hbit = (gt >> 4) & 1;
    const int rest = gt >> 5;
    r.d = ((rest & 31) << 4) + lane16;
    r.c = (rest >> 5) & (NC - 1);
    r.b = rest >> 12;
    r.s0 = r.hbit * SH;
    return r;
}

// ---------------------------------------------------------------------------
// K1: per-(b, chunk, d, s-half) thread — chunk transforms (Q, H).
//     (256,4): 64-reg cap, 4 CTAs/SM — measured optimum.
// ---------------------------------------------------------------------------
__global__ void __launch_bounds__(256, 4)
k_summary(const float* __restrict__ u, const float* __restrict__ dt,
          const float* __restrict__ Bin,
          const float* __restrict__ A_log, const float* __restrict__ A_i,
          const float* __restrict__ A_j,  const float* __restrict__ A_k)
{
    const DeH de = decompH(blockIdx.x * blockDim.x + threadIdx.x);
    const int d = de.d, c = de.c, b = de.b, s0 = de.s0;

    AInv av[SH];
#pragma unroll
    for (int s = 0; s < SH; s++)
        av[s] = load_ainv(A_log, A_i, A_j, A_k, d * SQ + s0 + s);

    const float4* __restrict__ u4 = (const float4*)u;
    const float4* __restrict__ B4 = (const float4*)Bin;

    const int t0 = c * CHUNKF;
    float4 Q[SH], H[SH];

    {   // peel first step: Q = q, H = q(x)Bu0 + Bu0
        const int td = b * LEN + t0;
        const float  dtv = dt[td * DQ + d];
        const float4 uu  = u4[td * DQ + d];
        const float  hdt = 0.5f * dtv;
        const float  dt2 = dtv * dtv;
        const float4 us  = make_float4(uu.x * hdt, uu.y * hdt, uu.z * hdt, uu.w * hdt);
#pragma unroll
        for (int s = 0; s < SH; s++) {
            const float4 Bq = B4[td * SQ + s0 + s];
            const float4 q  = step_q(dtv, dt2, av[s]);
            const float4 Bu0 = qmul(Bq, us);
            Q[s] = q;
            H[s] = qmuladd(q, Bu0, Bu0);
        }
    }

#pragma unroll 2
    for (int i = 1; i < CHUNKF; i++) {
        const int td = b * LEN + t0 + i;
        const float  dtv = dt[td * DQ + d];
        const float4 uu  = u4[td * DQ + d];
        const float  hdt = 0.5f * dtv;
        const float  dt2 = dtv * dtv;
        const float4 us  = make_float4(uu.x * hdt, uu.y * hdt, uu.z * hdt, uu.w * hdt);
#pragma unroll
        for (int s = 0; s < SH; s++) {
            const float4 Bq = B4[td * SQ + s0 + s];
            const float4 q  = step_q(dtv, dt2, av[s]);
            const float4 Bu0 = qmul(Bq, us);
            H[s] = qmuladd(q, add4(H[s], Bu0), Bu0);
            Q[s] = qmul(q, Q[s]);
        }
    }

#pragma unroll
    for (int s = 0; s < SH; s++) {
        const int idx = ((b * NC + c) * SQ + s0 + s) * DQ + d;
        __stcs(&g_Q[idx], Q[s]);           // scratch: streamed, read-once
        __stcs(&g_H[idx], H[s]);
    }
}

// ---------------------------------------------------------------------------
// K2: warp-parallel affine scan. One warp per (b,s,d) chain; each lane owns
//     NCL=4 consecutive fine chunks. Local compose -> shfl_up scan -> replay.
// ---------------------------------------------------------------------------
__global__ void __launch_bounds__(256)
k_carry()
{
    const int gt = blockIdx.x * blockDim.x + threadIdx.x;
    const int lane = gt & 31;
    const int w = gt >> 5;                 // chain id in [0, BSZ*SQ*DQ)
    const int d = w & (DQ - 1);
    const int s = (w >> 9) & (SQ - 1);
    const int b = w >> 11;

    const int cstride = SQ * DQ;
    const int base = (b * NC * SQ + s) * DQ + d;
    const int c0 = lane * NCL;

    float4 Qc[NCL], Hc[NCL];
#pragma unroll
    for (int j = 0; j < NCL; j++) {
        const int idx = base + (c0 + j) * cstride;
        Qc[j] = __ldcs(&g_Q[idx]);         // last read of this data
        Hc[j] = __ldcs(&g_H[idx]);
    }

    // Local inclusive composition over this lane's 4 chunks.
    float4 Qs = Qc[0], Hs = Hc[0];
#pragma unroll
    for (int j = 1; j < NCL; j++) {
        Hs = qmuladd(Qc[j], Hs, Hc[j]);
        Qs = qmul(Qc[j], Qs);
    }

    // Warp inclusive scan of the affine pair.
#pragma unroll
    for (int off = 1; off < 32; off <<= 1) {
        const float4 Qp = shfl_up4(Qs, off);
        const float4 Hp = shfl_up4(Hs, off);
        if (lane >= off) {
            Hs = qmuladd(Qs, Hp, Hs);   // pre-update Qs = current segment
            Qs = qmul(Qs, Qp);
        }
    }

    // Exclusive prefix = inclusive of lane-1 (identity at lane 0).
    float4 h = shfl_up4(Hs, 1);
    if (lane == 0) h = make_float4(0.f, 0.f, 0.f, 0.f);

    // Replay: emit carry-in for each owned chunk.
#pragma unroll
    for (int j = 0; j < NCL; j++) {
        const int idx = base + (c0 + j) * cstride;
        __stcs(&g_Hin[idx], h);            // scratch: streamed, read-once
        h = qmuladd(Qc[j], h, Hc[j]);
    }
}

// ---------------------------------------------------------------------------
// K3: per-(b, chunk, d, s-half) thread — recompute with carry, emit y.
//     Streaming policies: carry loads __ldcs, output stores __stcs.
// ---------------------------------------------------------------------------
__global__ void __launch_bounds__(256, 4)
k_final(const float* __restrict__ u, const float* __restrict__ dt,
        const float* __restrict__ Bin, const float* __restrict__ Cin,
        const float* __restrict__ A_log, const float* __restrict__ A_i,
        const float* __restrict__ A_j,  const float* __restrict__ A_k,
        float* __restrict__ out)
{
    const DeH de = decompH(blockIdx.x * blockDim.x + threadIdx.x);
    const int d = de.d, c = de.c, b = de.b, s0 = de.s0;

    AInv av[SH];
#pragma unroll
    for (int s = 0; s < SH; s++)
        av[s] = load_ainv(A_log, A_i, A_j, A_k, d * SQ + s0 + s);

    float4 h[SH];
#pragma unroll
    for (int s = 0; s < SH; s++)
        h[s] = __ldcs(&g_Hin[((b * NC + c) * SQ + s0 + s) * DQ + d]);

    const float4* __restrict__ u4 = (const float4*)u;
    const float4* __restrict__ B4 = (const float4*)Bin;
    const float4* __restrict__ C4 = (const float4*)Cin;
    float4* __restrict__ o4 = (float4*)out;

    const int t0 = c * CHUNKF;
#pragma unroll 2
    for (int i = 0; i < CHUNKF; i++) {
        const int td = b * LEN + t0 + i;
        const float  dtv = dt[td * DQ + d];
        const float4 uu  = u4[td * DQ + d];
        const float  hdt = 0.5f * dtv;
        const float  dt2 = dtv * dtv;
        const float4 us  = make_float4(uu.x * hdt, uu.y * hdt, uu.z * hdt, uu.w * hdt);
        float4 y = make_float4(0.f, 0.f, 0.f, 0.f);
#pragma unroll
        for (int s = 0; s < SH; s++) {
            const float4 Bq = B4[td * SQ + s0 + s];
            const float4 Cq = C4[td * SQ + s0 + s];
            const float4 q  = step_q(dtv, dt2, av[s]);
            const float4 Bu0 = qmul(Bq, us);
            h[s] = qmuladd(q, add4(h[s], Bu0), Bu0);
            y = qmuladd(Cq, h[s], y);
        }
        // Pair-reduce across s-halves (lane bit 4).
        y.x += __shfl_xor_sync(0xffffffffu, y.x, 16);
        y.y += __shfl_xor_sync(0xffffffffu, y.y, 16);
        y.z += __shfl_xor_sync(0xffffffffu, y.z, 16);
        y.w += __shfl_xor_sync(0xffffffffu, y.w, 16);
        if (de.hbit == 0)
            __stcs(&o4[td * DQ + d], y);   // streaming store: keep u/dt in L2
    }
}

// ---------------------------------------------------------------------------
// Launch (single stream)
// ---------------------------------------------------------------------------
extern "C" void kernel_launch(void* const* d_in, const int* in_sizes, int n_in,
                              void* d_out, int out_size)
{
    const float* u     = (const float*)d_in[0];
    const float* dt    = (const float*)d_in[1];
    const float* Bin   = (const float*)d_in[2];
    const float* Cin   = (const float*)d_in[3];
    const float* A_log = (const float*)d_in[4];
    const float* A_i   = (const float*)d_in[5];
    const float* A_j   = (const float*)d_in[6];
    const float* A_k   = (const float*)d_in[7];
    float* out = (float*)d_out;

    const int k13_threads = BSZ * NC * DQ * 2;      // 262144
    const int k2_threads  = BSZ * SQ * DQ * 32;     // 131072 (warp per chain)

    k_summary<<<k13_threads / 256, 256>>>(u, dt, Bin, A_log, A_i, A_j, A_k);
    k_carry<<<k2_threads / 256, 256>>>();
    k_final<<<k13_threads / 256, 256>>>(u, dt, Bin, Cin, A_log, A_i, A_j, A_k, out);
}